// round 5
// baseline (speedup 1.0000x reference)
#include <cuda_runtime.h>
#include <cstdint>

#define BB 32
#define TT_ 256
#define CHL 16
#define CE_ 64
#define HC_ 64
#define HW_ 256
#define EMB_ 300
#define EIN_ 428
#define XS_ 432
#define LL_ 32
#define NROW (BB*TT_)
#define NCHR (NROW*CHL)     // 131072

__device__ float g_char_rep[NROW*128];
__device__ float g_x[NROW*XS_];
// xg layout: [dir][t][p(64)][b(32)][gr(16)]  (gr = q*4+jj)
__device__ float g_xg[2][TT_*64*32*16];
__device__ float g_cxg[2][NCHR*256];
__device__ float g_hs[NROW*512];
__device__ float g_feats[NROW*LL_];
__device__ volatile unsigned g_flag[2][64];

__device__ __forceinline__ float sigf(float x) { return 1.0f/(1.0f+__expf(-x)); }
__device__ __forceinline__ float tanh_(float x) {
    x = fmaxf(x, -43.0f);
    float e = __expf(-2.0f*x);
    return (1.0f - e)/(1.0f + e);
}

__global__ void init_kernel() {
    int t = threadIdx.x;
    if (t < 128) g_flag[t >> 6][t & 63] = 0u;
}

// ================= 128x64 tile GEMM bodies (8x4 per-thread micro-tile) ==========
// As: [16][132], Bs: [16][68]

// ---- cxg[dir] = char_emb[cseq] @ Wih^T ----
__global__ void cxg_gemm_kernel(const int* __restrict__ cseq,
                                const float* __restrict__ char_emb,
                                const float* __restrict__ Wf,
                                const float* __restrict__ Wb)
{
    __shared__ float As[16*132];
    __shared__ float Bs[16*68];
    const int dir = blockIdx.z;
    const float* W = dir ? Wb : Wf;
    float* Cout = g_cxg[dir];
    const int m0 = blockIdx.x*128, n0 = blockIdx.y*64;
    const int tid = threadIdx.x;
    const int tm = tid >> 4, tn = tid & 15;
    const int ar = tid >> 1, ac = tid & 1;       // A loader: row, k-half
    const int br = tid >> 2, bc = tid & 3;       // B loader
    const int ci = cseq[m0 + ar];

    float acc[8][4];
    #pragma unroll
    for (int i = 0; i < 8; ++i)
        #pragma unroll
        for (int j = 0; j < 4; ++j) acc[i][j] = 0.f;

    #pragma unroll
    for (int kt = 0; kt < 4; ++kt) {
        const int k0 = kt*16;
        float4 a0 = ((const float4*)char_emb)[ci*16 + kt*4 + ac*2];
        float4 a1 = ((const float4*)char_emb)[ci*16 + kt*4 + ac*2 + 1];
        float4 bv = *(const float4*)&W[(n0+br)*64 + k0 + bc*4];
        As[(ac*8+0)*132+ar]=a0.x; As[(ac*8+1)*132+ar]=a0.y;
        As[(ac*8+2)*132+ar]=a0.z; As[(ac*8+3)*132+ar]=a0.w;
        As[(ac*8+4)*132+ar]=a1.x; As[(ac*8+5)*132+ar]=a1.y;
        As[(ac*8+6)*132+ar]=a1.z; As[(ac*8+7)*132+ar]=a1.w;
        Bs[(bc*4+0)*68+br]=bv.x; Bs[(bc*4+1)*68+br]=bv.y;
        Bs[(bc*4+2)*68+br]=bv.z; Bs[(bc*4+3)*68+br]=bv.w;
        __syncthreads();
        #pragma unroll
        for (int k = 0; k < 16; ++k) {
            float4 aA = ((float4*)&As[k*132])[tm*2];
            float4 aB = ((float4*)&As[k*132])[tm*2+1];
            float4 b4 = ((float4*)&Bs[k*68])[tn];
            float av[8] = {aA.x,aA.y,aA.z,aA.w,aB.x,aB.y,aB.z,aB.w};
            #pragma unroll
            for (int i = 0; i < 8; ++i) {
                acc[i][0] += av[i]*b4.x; acc[i][1] += av[i]*b4.y;
                acc[i][2] += av[i]*b4.z; acc[i][3] += av[i]*b4.w;
            }
        }
        __syncthreads();
    }
    #pragma unroll
    for (int i = 0; i < 8; ++i)
        *(float4*)&Cout[(m0+tm*8+i)*256 + n0 + tn*4] =
            make_float4(acc[i][0], acc[i][1], acc[i][2], acc[i][3]);
}

// ---- xg[dir] = x @ Wih^T, scattered epilogue into [t][p][b][gr] layout ----
__global__ void wih_gemm_kernel(const float* __restrict__ Wf,
                                const float* __restrict__ Wb)
{
    __shared__ float As[16*132];
    __shared__ float Bs[16*68];
    const int dir = blockIdx.z;
    const float* W = dir ? Wb : Wf;
    float* Cout = g_xg[dir];
    const int m0 = blockIdx.x*128, n0 = blockIdx.y*64;
    const int tid = threadIdx.x;
    const int tm = tid >> 4, tn = tid & 15;
    const int ar = tid >> 1, ac = tid & 1;
    const int br = tid >> 2, bc = tid & 3;

    float acc[8][4];
    #pragma unroll
    for (int i = 0; i < 8; ++i)
        #pragma unroll
        for (int j = 0; j < 4; ++j) acc[i][j] = 0.f;

    for (int k0 = 0; k0 < XS_; k0 += 16) {
        const float4* arow = (const float4*)&g_x[(m0+ar)*XS_ + k0];
        float4 a0 = arow[ac*2];
        float4 a1 = arow[ac*2+1];
        int kk = k0 + bc*4;
        float4 bv = make_float4(0.f,0.f,0.f,0.f);
        if (kk + 4 <= EIN_) bv = *(const float4*)&W[(n0+br)*EIN_ + kk];
        As[(ac*8+0)*132+ar]=a0.x; As[(ac*8+1)*132+ar]=a0.y;
        As[(ac*8+2)*132+ar]=a0.z; As[(ac*8+3)*132+ar]=a0.w;
        As[(ac*8+4)*132+ar]=a1.x; As[(ac*8+5)*132+ar]=a1.y;
        As[(ac*8+6)*132+ar]=a1.z; As[(ac*8+7)*132+ar]=a1.w;
        Bs[(bc*4+0)*68+br]=bv.x; Bs[(bc*4+1)*68+br]=bv.y;
        Bs[(bc*4+2)*68+br]=bv.z; Bs[(bc*4+3)*68+br]=bv.w;
        __syncthreads();
        #pragma unroll
        for (int k = 0; k < 16; ++k) {
            float4 aA = ((float4*)&As[k*132])[tm*2];
            float4 aB = ((float4*)&As[k*132])[tm*2+1];
            float4 b4 = ((float4*)&Bs[k*68])[tn];
            float av[8] = {aA.x,aA.y,aA.z,aA.w,aB.x,aB.y,aB.z,aB.w};
            #pragma unroll
            for (int i = 0; i < 8; ++i) {
                acc[i][0] += av[i]*b4.x; acc[i][1] += av[i]*b4.y;
                acc[i][2] += av[i]*b4.z; acc[i][3] += av[i]*b4.w;
            }
        }
        __syncthreads();
    }
    // scatter into [t][p][b][gr]
    #pragma unroll
    for (int i = 0; i < 8; ++i) {
        int m = m0 + tm*8 + i;
        int b = m >> 8, t = m & 255;
        #pragma unroll
        for (int j = 0; j < 4; ++j) {
            int n = n0 + tn*4 + j;
            int q = n >> 8, p = (n >> 2) & 63, jj = n & 3;
            Cout[((t*64 + p)*32 + b)*16 + q*4 + jj] = acc[i][j];
        }
    }
}

// ---- char recurrence: 8 seqs/block, only Whh in smem ----
__global__ void char_rec_kernel(
    const float* __restrict__ Whh_f, const float* __restrict__ bih_f, const float* __restrict__ bhh_f,
    const float* __restrict__ Whh_b, const float* __restrict__ bih_b, const float* __restrict__ bhh_b)
{
    extern __shared__ float sm[];
    const int P = 257;
    float* WhhT = sm;                 // [64][257]
    float* bsum = WhhT + 64*P;        // [256]
    float* hsm  = bsum + 256;         // [8][64]
    float* csm  = hsm + 512;          // [8][64]
    float* gts  = csm + 512;          // [8][256]

    const int dir = blockIdx.y;
    const float* Whh = dir ? Whh_b : Whh_f;
    const float* bih = dir ? bih_b : bih_f;
    const float* bhh = dir ? bhh_b : bhh_f;
    const float* cxg = g_cxg[dir];
    const int tid = threadIdx.x;

    for (int u = tid; u < 256*64; u += 256) {
        int g = u >> 6, k = u & 63;
        WhhT[k*P + g] = Whh[u];
    }
    bsum[tid] = bih[tid] + bhh[tid];
    for (int u = tid; u < 512; u += 256) { hsm[u] = 0.f; csm[u] = 0.f; }
    __syncthreads();

    const int g = tid;
    const int seq0 = blockIdx.x*8;
    for (int step = 0; step < 16; ++step) {
        int tcur = dir ? (15 - step) : step;
        float acc[8];
        #pragma unroll
        for (int s = 0; s < 8; ++s)
            acc[s] = bsum[g] + cxg[((seq0 + s)*16 + tcur)*256 + g];
        #pragma unroll 4
        for (int k4 = 0; k4 < 16; ++k4) {
            float w[4];
            #pragma unroll
            for (int j = 0; j < 4; ++j) w[j] = WhhT[(k4*4+j)*P + g];
            #pragma unroll
            for (int s = 0; s < 8; ++s) {
                float4 h = ((float4*)hsm)[s*16 + k4];
                acc[s] += w[0]*h.x + w[1]*h.y + w[2]*h.z + w[3]*h.w;
            }
        }
        #pragma unroll
        for (int s = 0; s < 8; ++s) gts[s*256 + g] = acc[s];
        __syncthreads();
        #pragma unroll
        for (int r = 0; r < 2; ++r) {
            int u = tid + r*256;
            int s = u >> 6, j = u & 63;
            float i_ = sigf(gts[s*256 + j]);
            float f_ = sigf(gts[s*256 + 64 + j]);
            float gg = tanh_(gts[s*256 + 128 + j]);
            float o_ = sigf(gts[s*256 + 192 + j]);
            float c = f_*csm[u] + i_*gg;
            csm[u] = c;
            hsm[u] = o_*tanh_(c);
        }
        __syncthreads();
    }
    int off = dir ? 0 : 64;   // [hb, hf]
    #pragma unroll
    for (int r = 0; r < 2; ++r) {
        int u = tid + r*256;
        int s = u >> 6, j = u & 63;
        g_char_rep[(seq0 + s)*128 + off + j] = hsm[u];
    }
}

// ---- x = [emb[sentence], char_rep], padded to 432 (vectorized) ----
__global__ void gather_x_kernel(const int* __restrict__ sentence,
                                const float* __restrict__ emb)
{
    int row = blockIdx.x, tid = threadIdx.x;
    int w = sentence[row];
    float4* xr = (float4*)&g_x[row*XS_];
    const float4* er = (const float4*)&emb[w*EMB_];        // 75 float4
    const float4* cr = (const float4*)&g_char_rep[row*128]; // 32 float4
    for (int k = tid; k < 75; k += 128) xr[k] = er[k];
    if (tid < 32) xr[75 + tid] = cr[tid];
    if (tid == 32) xr[107] = make_float4(0.f,0.f,0.f,0.f);
}

// ---- word BiLSTM: persistent 128 CTAs, flag barrier, xg prefetch ----
__global__ void word_lstm_kernel(
    const float* __restrict__ Whh_f, const float* __restrict__ Whh_b,
    const float* __restrict__ bih_f, const float* __restrict__ bhh_f,
    const float* __restrict__ bih_b, const float* __restrict__ bhh_b)
{
    extern __shared__ float sm[];
    float* W4s   = sm;            // [64 k4][16 gr] x float4
    float* h_s   = W4s + 4096;    // [32][256]
    float* gates = h_s + 8192;    // [32][16]
    float* c_s   = gates + 512;   // [32][4]
    float* bias  = c_s + 128;     // [16]

    const int tid = threadIdx.x;
    const int dir = blockIdx.x >> 6;
    const int p   = blockIdx.x & 63;
    const float* Whh = dir ? Whh_b : Whh_f;
    const float* bi  = dir ? bih_b : bih_f;
    const float* bh  = dir ? bhh_b : bhh_f;
    const float* xg  = g_xg[dir];

    for (int u = tid; u < 1024; u += 256) {
        int k4 = u >> 4, gr = u & 15;
        int grow = (gr >> 2)*256 + p*4 + (gr & 3);
        ((float4*)W4s)[k4*16 + gr] = *(const float4*)&Whh[grow*256 + k4*4];
    }
    if (tid < 16) {
        int grow = (tid >> 2)*256 + p*4 + (tid & 3);
        bias[tid] = bi[grow] + bh[grow];
    }
    if (tid < 128) c_s[tid] = 0.f;
    __syncthreads();

    const int gr = tid & 15, bp = tid >> 4;
    const int b1 = bp, b2 = bp + 16;

    int t0 = dir ? 255 : 0;
    float x1 = xg[((t0*64 + p)*32 + b1)*16 + gr];
    float x2 = xg[((t0*64 + p)*32 + b2)*16 + gr];

    for (int it = 0; it < 256; ++it) {
        int tcur = dir ? (255 - it) : it;
        if (it == 0) {
            for (int u = tid; u < 8192; u += 256) h_s[u] = 0.f;
        } else {
            int tprev = dir ? (tcur + 1) : (tcur - 1);
            for (int u = tid; u < 2048; u += 256) {
                int b = u >> 6, k4 = u & 63;
                ((float4*)h_s)[b*64 + k4] =
                    __ldcg((const float4*)&g_hs[(b*256 + tprev)*512 + dir*256 + k4*4]);
            }
        }
        __syncthreads();

        float a1 = bias[gr] + x1;
        float a2 = bias[gr] + x2;
        // prefetch next step's x early so LDG latency hides under FMA loop
        if (it < 255) {
            int tn_ = dir ? (tcur - 1) : (tcur + 1);
            x1 = xg[((tn_*64 + p)*32 + b1)*16 + gr];
            x2 = xg[((tn_*64 + p)*32 + b2)*16 + gr];
        }
        #pragma unroll 8
        for (int k4 = 0; k4 < 64; ++k4) {
            float4 w  = ((float4*)W4s)[k4*16 + gr];
            float4 hA = ((float4*)h_s)[b1*64 + k4];
            float4 hB = ((float4*)h_s)[b2*64 + k4];
            a1 += w.x*hA.x + w.y*hA.y + w.z*hA.z + w.w*hA.w;
            a2 += w.x*hB.x + w.y*hB.y + w.z*hB.z + w.w*hB.w;
        }
        gates[b1*16 + gr] = a1;
        gates[b2*16 + gr] = a2;
        __syncthreads();

        if (tid < 128) {
            int b = tid >> 2, j2 = tid & 3;
            float i_ = sigf(gates[b*16 + j2]);
            float f_ = sigf(gates[b*16 + 4 + j2]);
            float gg = tanh_(gates[b*16 + 8 + j2]);
            float o_ = sigf(gates[b*16 + 12 + j2]);
            float c = f_*c_s[tid] + i_*gg;
            c_s[tid] = c;
            __stcg(&g_hs[(b*256 + tcur)*512 + dir*256 + p*4 + j2], o_*tanh_(c));
        }
        __syncthreads();
        if (tid == 0) {
            __threadfence();
            g_flag[dir][p] = (unsigned)(it + 1);   // volatile release-ish store
        }
        if (tid < 64) {
            while (g_flag[dir][tid] < (unsigned)(it + 1)) { }
        }
        __syncthreads();
    }
}

// ---- feats = hs @ projW^T + b ----
__global__ void proj_kernel(const float* __restrict__ projW,
                            const float* __restrict__ projb)
{
    extern __shared__ float sm[];
    float* pw = sm;               // [512][33]
    float* hr = pw + 512*33;      // [8][512]
    const int tid = threadIdx.x;
    for (int u = tid; u < 32*512; u += 256) {
        int l = u >> 9, k = u & 511;
        pw[k*33 + l] = projW[u];
    }
    int row0 = blockIdx.x*8;
    for (int u = tid; u < 1024; u += 256)
        ((float4*)hr)[u] = ((const float4*)&g_hs[row0*512])[u];
    __syncthreads();

    int r = tid >> 5, l = tid & 31;
    float acc = projb[l];
    #pragma unroll 4
    for (int k4 = 0; k4 < 128; ++k4) {
        float4 h4 = ((float4*)hr)[r*128 + k4];
        acc += h4.x*pw[(k4*4+0)*33 + l] + h4.y*pw[(k4*4+1)*33 + l]
             + h4.z*pw[(k4*4+2)*33 + l] + h4.w*pw[(k4*4+3)*33 + l];
    }
    g_feats[(row0 + r)*32 + l] = acc;
}

// ---- viterbi: one warp per batch element ----
__global__ void viterbi_kernel(const float* __restrict__ trans, float* __restrict__ out)
{
    __shared__ float fv[32];
    __shared__ float tr[32*33];
    __shared__ unsigned char bpv[256*32];
    const int l = threadIdx.x, b = blockIdx.x;
    for (int u = l; u < 1024; u += 32) tr[(u>>5)*33 + (u&31)] = trans[u];
    fv[l] = -10000.0f;
    __syncwarp();

    for (int t = 0; t < 256; ++t) {
        float m = -1e30f; int am = 0;
        #pragma unroll
        for (int pi = 0; pi < 32; ++pi) {
            float s = fv[pi] + tr[l*33 + pi];
            if (s > m) { m = s; am = pi; }
        }
        bpv[t*32 + l] = (unsigned char)am;
        float nf = m + g_feats[(b*256 + t)*32 + l];
        __syncwarp();
        fv[l] = nf;
        __syncwarp();
    }
    if (l == 0) {
        float bm = fv[0]; int bt = 0;
        for (int pi = 1; pi < 32; ++pi) if (fv[pi] > bm) { bm = fv[pi]; bt = pi; }
        out[b] = bm;
        int tag = bt;
        for (int t = 255; t >= 0; --t) {
            out[32 + b*256 + t] = (float)tag;
            tag = (int)bpv[t*32 + tag];
        }
    }
}

extern "C" void kernel_launch(void* const* d_in, const int* in_sizes, int n_in,
                              void* d_out, int out_size)
{
    const int* sent = (const int*)d_in[0];
    const int* cseq = (const int*)d_in[1];
    const float* const* F = (const float* const*)(d_in + 2);
    // F: 0 emb, 1 char_emb, 2..5 cWih_f,cWhh_f,cbih_f,cbhh_f, 6..9 backward,
    //    10..13 wWih_f,wWhh_f,wbih_f,wbhh_f, 14..17 backward, 18 proj_W, 19 proj_b, 20 trans
    float* out = (float*)d_out;

    cudaFuncSetAttribute(char_rec_kernel,  cudaFuncAttributeMaxDynamicSharedMemorySize, 100000);
    cudaFuncSetAttribute(word_lstm_kernel, cudaFuncAttributeMaxDynamicSharedMemorySize, 53000);
    cudaFuncSetAttribute(proj_kernel,      cudaFuncAttributeMaxDynamicSharedMemorySize, 90000);

    init_kernel<<<1, 128>>>();
    cxg_gemm_kernel<<<dim3(NCHR/128, 256/64, 2), 256>>>(cseq, F[1], F[2], F[6]);
    char_rec_kernel<<<dim3(NROW/8, 2), 256, 79104>>>(F[3], F[4], F[5], F[7], F[8], F[9]);
    gather_x_kernel<<<NROW, 128>>>(sent, F[0]);
    wih_gemm_kernel<<<dim3(NROW/128, 1024/64, 2), 256>>>(F[10], F[14]);
    word_lstm_kernel<<<128, 256, 51776>>>(F[11], F[15], F[12], F[13], F[16], F[17]);
    proj_kernel<<<NROW/8, 256, 83968>>>(F[18], F[19]);
    viterbi_kernel<<<BB, 32>>>(F[20], out);
}

// round 6
// speedup vs baseline: 1.2022x; 1.2022x over previous
#include <cuda_runtime.h>
#include <cstdint>

#define BB 32
#define TT_ 256
#define CHL 16
#define CE_ 64
#define HC_ 64
#define HW_ 256
#define EMB_ 300
#define EIN_ 428
#define XS_ 432
#define LL_ 32
#define NROW (BB*TT_)
#define NCHR (NROW*CHL)     // 131072

__device__ float g_x[NROW*XS_];
// xg layout: [dir][t][p(64)][b(32)][gr(16)]  (gr = q*4+jj)
__device__ float g_xg[2][TT_*64*32*16];
__device__ float g_cxg[2][NCHR*256];
__device__ float g_hs[NROW*512];
__device__ float g_feats[NROW*LL_];
__device__ unsigned g_cnt[2];
__device__ volatile unsigned g_epoch[2];

__device__ __forceinline__ float sigf(float x) { return 1.0f/(1.0f+__expf(-x)); }
__device__ __forceinline__ float tanh_(float x) {
    x = fmaxf(x, -43.0f);
    float e = __expf(-2.0f*x);
    return (1.0f - e)/(1.0f + e);
}

// ---- cxg[dir] = char_emb[cseq] @ Wih^T (128x64 tile, 8x4 micro-tile) ----
// block 0 also resets the word-lstm barrier state (graph-replay determinism)
__global__ void cxg_gemm_kernel(const int* __restrict__ cseq,
                                const float* __restrict__ char_emb,
                                const float* __restrict__ Wf,
                                const float* __restrict__ Wb)
{
    __shared__ float As[16*132];
    __shared__ float Bs[16*68];
    if (blockIdx.x == 0 && blockIdx.y == 0 && blockIdx.z == 0 && threadIdx.x < 2) {
        g_cnt[threadIdx.x] = 0u;
        g_epoch[threadIdx.x] = 0u;
    }
    const int dir = blockIdx.z;
    const float* W = dir ? Wb : Wf;
    float* Cout = g_cxg[dir];
    const int m0 = blockIdx.x*128, n0 = blockIdx.y*64;
    const int tid = threadIdx.x;
    const int tm = tid >> 4, tn = tid & 15;
    const int ar = tid >> 1, ac = tid & 1;
    const int br = tid >> 2, bc = tid & 3;
    const int ci = cseq[m0 + ar];

    float acc[8][4];
    #pragma unroll
    for (int i = 0; i < 8; ++i)
        #pragma unroll
        for (int j = 0; j < 4; ++j) acc[i][j] = 0.f;

    #pragma unroll
    for (int kt = 0; kt < 4; ++kt) {
        const int k0 = kt*16;
        float4 a0 = ((const float4*)char_emb)[ci*16 + kt*4 + ac*2];
        float4 a1 = ((const float4*)char_emb)[ci*16 + kt*4 + ac*2 + 1];
        float4 bv = *(const float4*)&W[(n0+br)*64 + k0 + bc*4];
        As[(ac*8+0)*132+ar]=a0.x; As[(ac*8+1)*132+ar]=a0.y;
        As[(ac*8+2)*132+ar]=a0.z; As[(ac*8+3)*132+ar]=a0.w;
        As[(ac*8+4)*132+ar]=a1.x; As[(ac*8+5)*132+ar]=a1.y;
        As[(ac*8+6)*132+ar]=a1.z; As[(ac*8+7)*132+ar]=a1.w;
        Bs[(bc*4+0)*68+br]=bv.x; Bs[(bc*4+1)*68+br]=bv.y;
        Bs[(bc*4+2)*68+br]=bv.z; Bs[(bc*4+3)*68+br]=bv.w;
        __syncthreads();
        #pragma unroll
        for (int k = 0; k < 16; ++k) {
            float4 aA = ((float4*)&As[k*132])[tm*2];
            float4 aB = ((float4*)&As[k*132])[tm*2+1];
            float4 b4 = ((float4*)&Bs[k*68])[tn];
            float av[8] = {aA.x,aA.y,aA.z,aA.w,aB.x,aB.y,aB.z,aB.w};
            #pragma unroll
            for (int i = 0; i < 8; ++i) {
                acc[i][0] += av[i]*b4.x; acc[i][1] += av[i]*b4.y;
                acc[i][2] += av[i]*b4.z; acc[i][3] += av[i]*b4.w;
            }
        }
        __syncthreads();
    }
    #pragma unroll
    for (int i = 0; i < 8; ++i)
        *(float4*)&Cout[(m0+tm*8+i)*256 + n0 + tn*4] =
            make_float4(acc[i][0], acc[i][1], acc[i][2], acc[i][3]);
}

// ---- char recurrence + x assembly: 8 seqs/block, dir = blockIdx.y ----
// writes its final h directly into g_x; dir==1 blocks also copy word emb + pad
__global__ void char_rec_kernel(
    const float* __restrict__ Whh_f, const float* __restrict__ bih_f, const float* __restrict__ bhh_f,
    const float* __restrict__ Whh_b, const float* __restrict__ bih_b, const float* __restrict__ bhh_b,
    const int* __restrict__ sentence, const float* __restrict__ emb)
{
    extern __shared__ float sm[];
    const int P = 257;
    float* WhhT = sm;                 // [64][257]
    float* bsum = WhhT + 64*P;        // [256]
    float* hsm  = bsum + 256;         // [8][64]
    float* csm  = hsm + 512;          // [8][64]
    float* gts  = csm + 512;          // [8][256]

    const int dir = blockIdx.y;
    const float* Whh = dir ? Whh_b : Whh_f;
    const float* bih = dir ? bih_b : bih_f;
    const float* bhh = dir ? bhh_b : bhh_f;
    const float* cxg = g_cxg[dir];
    const int tid = threadIdx.x;
    const int seq0 = blockIdx.x*8;

    for (int u = tid; u < 256*64; u += 256) {
        int g = u >> 6, k = u & 63;
        WhhT[k*P + g] = Whh[u];
    }
    bsum[tid] = bih[tid] + bhh[tid];
    for (int u = tid; u < 512; u += 256) { hsm[u] = 0.f; csm[u] = 0.f; }
    __syncthreads();

    const int g = tid;
    for (int step = 0; step < 16; ++step) {
        int tcur = dir ? (15 - step) : step;
        float acc[8];
        #pragma unroll
        for (int s = 0; s < 8; ++s)
            acc[s] = bsum[g] + cxg[((seq0 + s)*16 + tcur)*256 + g];
        #pragma unroll 4
        for (int k4 = 0; k4 < 16; ++k4) {
            float w[4];
            #pragma unroll
            for (int j = 0; j < 4; ++j) w[j] = WhhT[(k4*4+j)*P + g];
            #pragma unroll
            for (int s = 0; s < 8; ++s) {
                float4 h = ((float4*)hsm)[s*16 + k4];
                acc[s] += w[0]*h.x + w[1]*h.y + w[2]*h.z + w[3]*h.w;
            }
        }
        #pragma unroll
        for (int s = 0; s < 8; ++s) gts[s*256 + g] = acc[s];
        __syncthreads();
        #pragma unroll
        for (int r = 0; r < 2; ++r) {
            int u = tid + r*256;
            int s = u >> 6, j = u & 63;
            float i_ = sigf(gts[s*256 + j]);
            float f_ = sigf(gts[s*256 + 64 + j]);
            float gg = tanh_(gts[s*256 + 128 + j]);
            float o_ = sigf(gts[s*256 + 192 + j]);
            float c = f_*csm[u] + i_*gg;
            csm[u] = c;
            hsm[u] = o_*tanh_(c);
        }
        __syncthreads();
    }

    // x = [we(300), hb(64), hf(64), pad(4)]
    const int off = 300 + (dir ? 0 : 64);   // dir=1 -> hb, dir=0 -> hf
    #pragma unroll
    for (int r = 0; r < 2; ++r) {
        int u = tid + r*256;
        int s = u >> 6, j = u & 63;
        g_x[(seq0 + s)*XS_ + off + j] = hsm[u];
    }
    if (dir == 1) {
        for (int u = tid; u < 600; u += 256) {       // 8 rows x 75 float4
            int s = u / 75, f4 = u % 75;
            int row = seq0 + s;
            int w = sentence[row];
            ((float4*)&g_x[row*XS_])[f4] = ((const float4*)&emb[w*EMB_])[f4];
        }
        if (tid < 8)
            *(float4*)&g_x[(seq0 + tid)*XS_ + 428] = make_float4(0.f,0.f,0.f,0.f);
    }
}

// ---- xg[dir] = x @ Wih^T, float4 scatter epilogue into [t][p][b][gr] ----
__global__ void wih_gemm_kernel(const float* __restrict__ Wf,
                                const float* __restrict__ Wb)
{
    __shared__ float As[16*132];
    __shared__ float Bs[16*68];
    const int dir = blockIdx.z;
    const float* W = dir ? Wb : Wf;
    float* Cout = g_xg[dir];
    const int m0 = blockIdx.x*128, n0 = blockIdx.y*64;
    const int tid = threadIdx.x;
    const int tm = tid >> 4, tn = tid & 15;
    const int ar = tid >> 1, ac = tid & 1;
    const int br = tid >> 2, bc = tid & 3;

    float acc[8][4];
    #pragma unroll
    for (int i = 0; i < 8; ++i)
        #pragma unroll
        for (int j = 0; j < 4; ++j) acc[i][j] = 0.f;

    for (int k0 = 0; k0 < XS_; k0 += 16) {
        const float4* arow = (const float4*)&g_x[(m0+ar)*XS_ + k0];
        float4 a0 = arow[ac*2];
        float4 a1 = arow[ac*2+1];
        int kk = k0 + bc*4;
        float4 bv = make_float4(0.f,0.f,0.f,0.f);
        if (kk + 4 <= EIN_) bv = *(const float4*)&W[(n0+br)*EIN_ + kk];
        As[(ac*8+0)*132+ar]=a0.x; As[(ac*8+1)*132+ar]=a0.y;
        As[(ac*8+2)*132+ar]=a0.z; As[(ac*8+3)*132+ar]=a0.w;
        As[(ac*8+4)*132+ar]=a1.x; As[(ac*8+5)*132+ar]=a1.y;
        As[(ac*8+6)*132+ar]=a1.z; As[(ac*8+7)*132+ar]=a1.w;
        Bs[(bc*4+0)*68+br]=bv.x; Bs[(bc*4+1)*68+br]=bv.y;
        Bs[(bc*4+2)*68+br]=bv.z; Bs[(bc*4+3)*68+br]=bv.w;
        __syncthreads();
        #pragma unroll
        for (int k = 0; k < 16; ++k) {
            float4 aA = ((float4*)&As[k*132])[tm*2];
            float4 aB = ((float4*)&As[k*132])[tm*2+1];
            float4 b4 = ((float4*)&Bs[k*68])[tn];
            float av[8] = {aA.x,aA.y,aA.z,aA.w,aB.x,aB.y,aB.z,aB.w};
            #pragma unroll
            for (int i = 0; i < 8; ++i) {
                acc[i][0] += av[i]*b4.x; acc[i][1] += av[i]*b4.y;
                acc[i][2] += av[i]*b4.z; acc[i][3] += av[i]*b4.w;
            }
        }
        __syncthreads();
    }
    // [t][p][b][gr]: the 4 j-values are one aligned float4 (no 256-boundary cross)
    const int n = n0 + tn*4;
    const int q = n >> 8, p = (n >> 2) & 63;
    #pragma unroll
    for (int i = 0; i < 8; ++i) {
        int m = m0 + tm*8 + i;
        int b = m >> 8, t = m & 255;
        *(float4*)&Cout[((t*64 + p)*32 + b)*16 + q*4] =
            make_float4(acc[i][0], acc[i][1], acc[i][2], acc[i][3]);
    }
}

// ---- word BiLSTM: persistent 128 CTAs, tid0 atomic-epoch barrier ----
__global__ void word_lstm_kernel(
    const float* __restrict__ Whh_f, const float* __restrict__ Whh_b,
    const float* __restrict__ bih_f, const float* __restrict__ bhh_f,
    const float* __restrict__ bih_b, const float* __restrict__ bhh_b)
{
    extern __shared__ float sm[];
    float* W4s   = sm;            // [64 k4][16 gr] x float4
    float* h_s   = W4s + 4096;    // [32][256]
    float* gates = h_s + 8192;    // [32][16]
    float* c_s   = gates + 512;   // [32][4]
    float* bias  = c_s + 128;     // [16]

    const int tid = threadIdx.x;
    const int dir = blockIdx.x >> 6;
    const int p   = blockIdx.x & 63;
    const float* Whh = dir ? Whh_b : Whh_f;
    const float* bi  = dir ? bih_b : bih_f;
    const float* bh  = dir ? bhh_b : bhh_f;
    const float* xg  = g_xg[dir];

    for (int u = tid; u < 1024; u += 256) {
        int k4 = u >> 4, gr = u & 15;
        int grow = (gr >> 2)*256 + p*4 + (gr & 3);
        ((float4*)W4s)[k4*16 + gr] = *(const float4*)&Whh[grow*256 + k4*4];
    }
    if (tid < 16) {
        int grow = (tid >> 2)*256 + p*4 + (tid & 3);
        bias[tid] = bi[grow] + bh[grow];
    }
    if (tid < 128) c_s[tid] = 0.f;
    __syncthreads();

    const int gr = tid & 15, bp = tid >> 4;
    const int b1 = bp, b2 = bp + 16;

    int t0 = dir ? 255 : 0;
    float x1 = xg[((t0*64 + p)*32 + b1)*16 + gr];
    float x2 = xg[((t0*64 + p)*32 + b2)*16 + gr];

    for (int it = 0; it < 256; ++it) {
        int tcur = dir ? (255 - it) : it;
        if (it == 0) {
            for (int u = tid; u < 8192; u += 256) h_s[u] = 0.f;
        } else {
            int tprev = dir ? (tcur + 1) : (tcur - 1);
            for (int u = tid; u < 2048; u += 256) {
                int b = u >> 6, k4 = u & 63;
                ((float4*)h_s)[b*64 + k4] =
                    __ldcg((const float4*)&g_hs[(b*256 + tprev)*512 + dir*256 + k4*4]);
            }
        }
        __syncthreads();

        float a1 = bias[gr] + x1;
        float a2 = bias[gr] + x2;
        if (it < 255) {
            int tn_ = dir ? (tcur - 1) : (tcur + 1);
            x1 = xg[((tn_*64 + p)*32 + b1)*16 + gr];
            x2 = xg[((tn_*64 + p)*32 + b2)*16 + gr];
        }
        #pragma unroll 8
        for (int k4 = 0; k4 < 64; ++k4) {
            float4 w  = ((float4*)W4s)[k4*16 + gr];
            float4 hA = ((float4*)h_s)[b1*64 + k4];
            float4 hB = ((float4*)h_s)[b2*64 + k4];
            a1 += w.x*hA.x + w.y*hA.y + w.z*hA.z + w.w*hA.w;
            a2 += w.x*hB.x + w.y*hB.y + w.z*hB.z + w.w*hB.w;
        }
        gates[b1*16 + gr] = a1;
        gates[b2*16 + gr] = a2;
        __syncthreads();

        if (tid < 128) {
            int b = tid >> 2, j2 = tid & 3;
            float i_ = sigf(gates[b*16 + j2]);
            float f_ = sigf(gates[b*16 + 4 + j2]);
            float gg = tanh_(gates[b*16 + 8 + j2]);
            float o_ = sigf(gates[b*16 + 12 + j2]);
            float c = f_*c_s[tid] + i_*gg;
            c_s[tid] = c;
            __stcg(&g_hs[(b*256 + tcur)*512 + dir*256 + p*4 + j2], o_*tanh_(c));
        }
        __syncthreads();
        if (tid == 0) {
            __threadfence();
            unsigned old = atomicAdd(&g_cnt[dir], 1u);
            if (old == 64u*(unsigned)(it+1) - 1u) {
                __threadfence();
                g_epoch[dir] = (unsigned)(it + 1);
            }
            while (g_epoch[dir] < (unsigned)(it + 1)) { }
            __threadfence();
        }
        __syncthreads();
    }
}

// ---- feats = hs @ projW^T + b ----
__global__ void proj_kernel(const float* __restrict__ projW,
                            const float* __restrict__ projb)
{
    extern __shared__ float sm[];
    float* pw = sm;               // [512][33]
    float* hr = pw + 512*33;      // [8][512]
    const int tid = threadIdx.x;
    for (int u = tid; u < 32*512; u += 256) {
        int l = u >> 9, k = u & 511;
        pw[k*33 + l] = projW[u];
    }
    int row0 = blockIdx.x*8;
    for (int u = tid; u < 1024; u += 256)
        ((float4*)hr)[u] = ((const float4*)&g_hs[row0*512])[u];
    __syncthreads();

    int r = tid >> 5, l = tid & 31;
    float acc = projb[l];
    #pragma unroll 4
    for (int k4 = 0; k4 < 128; ++k4) {
        float4 h4 = ((float4*)hr)[r*128 + k4];
        acc += h4.x*pw[(k4*4+0)*33 + l] + h4.y*pw[(k4*4+1)*33 + l]
             + h4.z*pw[(k4*4+2)*33 + l] + h4.w*pw[(k4*4+3)*33 + l];
    }
    g_feats[(row0 + r)*32 + l] = acc;
}

// ---- viterbi: one warp per batch element ----
__global__ void viterbi_kernel(const float* __restrict__ trans, float* __restrict__ out)
{
    __shared__ float fv[32];
    __shared__ float tr[32*33];
    __shared__ unsigned char bpv[256*32];
    const int l = threadIdx.x, b = blockIdx.x;
    for (int u = l; u < 1024; u += 32) tr[(u>>5)*33 + (u&31)] = trans[u];
    fv[l] = -10000.0f;
    __syncwarp();

    for (int t = 0; t < 256; ++t) {
        float m = -1e30f; int am = 0;
        #pragma unroll
        for (int pi = 0; pi < 32; ++pi) {
            float s = fv[pi] + tr[l*33 + pi];
            if (s > m) { m = s; am = pi; }
        }
        bpv[t*32 + l] = (unsigned char)am;
        float nf = m + g_feats[(b*256 + t)*32 + l];
        __syncwarp();
        fv[l] = nf;
        __syncwarp();
    }
    if (l == 0) {
        float bm = fv[0]; int bt = 0;
        for (int pi = 1; pi < 32; ++pi) if (fv[pi] > bm) { bm = fv[pi]; bt = pi; }
        out[b] = bm;
        int tag = bt;
        for (int t = 255; t >= 0; --t) {
            out[32 + b*256 + t] = (float)tag;
            tag = (int)bpv[t*32 + tag];
        }
    }
}

extern "C" void kernel_launch(void* const* d_in, const int* in_sizes, int n_in,
                              void* d_out, int out_size)
{
    const int* sent = (const int*)d_in[0];
    const int* cseq = (const int*)d_in[1];
    const float* const* F = (const float* const*)(d_in + 2);
    // F: 0 emb, 1 char_emb, 2..5 cWih_f,cWhh_f,cbih_f,cbhh_f, 6..9 backward,
    //    10..13 wWih_f,wWhh_f,wbih_f,wbhh_f, 14..17 backward, 18 proj_W, 19 proj_b, 20 trans
    float* out = (float*)d_out;

    cudaFuncSetAttribute(char_rec_kernel,  cudaFuncAttributeMaxDynamicSharedMemorySize, 100000);
    cudaFuncSetAttribute(word_lstm_kernel, cudaFuncAttributeMaxDynamicSharedMemorySize, 53000);
    cudaFuncSetAttribute(proj_kernel,      cudaFuncAttributeMaxDynamicSharedMemorySize, 90000);

    cxg_gemm_kernel<<<dim3(NCHR/128, 4, 2), 256>>>(cseq, F[1], F[2], F[6]);
    char_rec_kernel<<<dim3(NROW/8, 2), 256, 79104>>>(
        F[3], F[4], F[5], F[7], F[8], F[9], sent, F[0]);
    wih_gemm_kernel<<<dim3(NROW/128, 1024/64, 2), 256>>>(F[10], F[14]);
    word_lstm_kernel<<<128, 256, 51776>>>(F[11], F[15], F[12], F[13], F[16], F[17]);
    proj_kernel<<<NROW/8, 256, 83968>>>(F[18], F[19]);
    viterbi_kernel<<<BB, 32>>>(F[20], out);
}